// round 13
// baseline (speedup 1.0000x reference)
#include <cuda_runtime.h>
#include <math.h>

#define N_DIM    64
#define B_ROWS   1024
#define QCH      32
#define NGRP     16                // knn row-groups of 64
#define NQ       16                // j-sixteenths (64 js each)
#define NBLK_KNN (NGRP * NQ)       // 256
#define NBLK_K2  512               // 64 cols x 8; 4 chunks x 2 warps per block
#define TS       3.5f              // truncation radius, h-units
#define K2C      (-0.72134752f)    // -0.5*log2(e)
#define NMOM     11                // Hermite terms 0..10

// Scratch (device globals — no allocation allowed)
__device__ float g_logrho[B_ROWS];
__device__ float g_cols[N_DIM * B_ROWS];   // sorted columns, scaled by 1/h
__device__ float g_invh[N_DIM];
__device__ float g_partials[N_DIM * QCH];
__device__ float g_t6[NGRP][NQ][64][6];
__device__ int   g_qc[NGRP];               // self-resetting sixteenth counters
__device__ int   g_done;                   // reset by k1 block 0 each run

__device__ __forceinline__ float ex2(float x) {
    float r;
    asm("ex2.approx.ftz.f32 %0, %1;" : "=f"(r) : "f"(x));
    return r;
}

// ---------------------------------------------------------------------------
// Kernel 1: knn (blocks 0..255) + prep (blocks 256..319), 256 threads.
// knn block: 64 rows (8/warp), 64 js (2/lane); fused shuffle norms.
// ---------------------------------------------------------------------------
struct KnnS {
    float tile[64][68];    // stride 68: conflict-free LDS.128
    float xq[64][64];
    float jn[64];
    float qn[64];
    int   merge;
};
struct PrepS {
    float u[B_ROWS];
    float red[256];
    float scale;
};

__global__ __launch_bounds__(256)
void k1(const float* __restrict__ act, const int* __restrict__ kp) {
    __shared__ __align__(16) char sm[sizeof(KnnS) > sizeof(PrepS) ? sizeof(KnnS) : sizeof(PrepS)];
    const int tid = threadIdx.x;
    const int bx  = blockIdx.x;

    if (bx == 0 && tid == 0) g_done = 0;

    if (bx < NBLK_KNN) {
        KnnS* S = (KnnS*)sm;
        const int g = bx >> 4, q = bx & 15;
        const int row0 = g * 64, jbase = q * 64;
        const int lane = tid & 31, w = tid >> 5;

        // 64 query rows + norms (16-lane shuffle reduce; 16 float4 per row)
        {
            const float4* qsrc = (const float4*)(act + row0 * N_DIM);
            #pragma unroll
            for (int t = 0; t < 4; t++) {
                int fi = tid + t * 256;
                float4 v = qsrc[fi];
                ((float4*)S->xq)[fi] = v;
                float s = v.x * v.x + v.y * v.y + v.z * v.z + v.w * v.w;
                s += __shfl_down_sync(0xffffffffu, s, 8, 16);
                s += __shfl_down_sync(0xffffffffu, s, 4, 16);
                s += __shfl_down_sync(0xffffffffu, s, 2, 16);
                s += __shfl_down_sync(0xffffffffu, s, 1, 16);
                if ((lane & 15) == 0) S->qn[fi >> 4] = s;
            }
        }
        // 64-row j tile + norms fused
        {
            const float4* gsrc = (const float4*)(act + jbase * N_DIM);
            #pragma unroll
            for (int t = 0; t < 4; t++) {
                int fi = tid + t * 256;
                float4 v = gsrc[fi];
                *(float4*)&S->tile[fi >> 4][(fi & 15) * 4] = v;
                float s = v.x * v.x + v.y * v.y + v.z * v.z + v.w * v.w;
                s += __shfl_down_sync(0xffffffffu, s, 8, 16);
                s += __shfl_down_sync(0xffffffffu, s, 4, 16);
                s += __shfl_down_sync(0xffffffffu, s, 2, 16);
                s += __shfl_down_sync(0xffffffffu, s, 1, 16);
                if ((lane & 15) == 0) S->jn[fi >> 4] = s;
            }
        }
        __syncthreads();

        float acc[8][2];
        #pragma unroll
        for (int r = 0; r < 8; r++) { acc[r][0] = 0.f; acc[r][1] = 0.f; }

        #pragma unroll
        for (int c = 0; c < 8; c++) {          // 8-dim chunks
            const float4 b00 = *(const float4*)&S->tile[lane][c * 8];
            const float4 b01 = *(const float4*)&S->tile[lane][c * 8 + 4];
            const float4 b10 = *(const float4*)&S->tile[lane + 32][c * 8];
            const float4 b11 = *(const float4*)&S->tile[lane + 32][c * 8 + 4];
            #pragma unroll
            for (int r = 0; r < 8; r++) {
                const float4 q0 = *(const float4*)&S->xq[8 * w + r][c * 8];
                const float4 q1 = *(const float4*)&S->xq[8 * w + r][c * 8 + 4];
                float a = acc[r][0], b = acc[r][1];
                a = fmaf(q0.x, b00.x, a); b = fmaf(q0.x, b10.x, b);
                a = fmaf(q0.y, b00.y, a); b = fmaf(q0.y, b10.y, b);
                a = fmaf(q0.z, b00.z, a); b = fmaf(q0.z, b10.z, b);
                a = fmaf(q0.w, b00.w, a); b = fmaf(q0.w, b10.w, b);
                a = fmaf(q1.x, b01.x, a); b = fmaf(q1.x, b11.x, b);
                a = fmaf(q1.y, b01.y, a); b = fmaf(q1.y, b11.y, b);
                a = fmaf(q1.z, b01.z, a); b = fmaf(q1.z, b11.z, b);
                a = fmaf(q1.w, b01.w, a); b = fmaf(q1.w, b11.w, b);
                acc[r][0] = a; acc[r][1] = b;
            }
        }

        // per row: 2 candidates per lane -> sorted pair, extract top-6 of warp
        const float nj0 = S->jn[lane], nj1 = S->jn[lane + 32];
        #pragma unroll
        for (int r = 0; r < 8; r++) {
            float v0 = fmaf(acc[r][0], -2.f, nj0);
            float v1 = fmaf(acc[r][1], -2.f, nj1);
            float l0 = fminf(v0, v1), l1 = fmaxf(v0, v1);
            float keep = 3.4e38f;
            #pragma unroll
            for (int i = 0; i < 6; i++) {
                float mv = l0;
                #pragma unroll
                for (int off = 16; off; off >>= 1)
                    mv = fminf(mv, __shfl_xor_sync(0xffffffffu, mv, off));
                if (lane == i) keep = mv;
                unsigned msk = __ballot_sync(0xffffffffu, l0 == mv);
                if (lane == (__ffs(msk) - 1)) { l0 = l1; l1 = 3.4e38f; }
            }
            if (lane < 6)
                g_t6[g][q][8 * w + r][lane] = keep + S->qn[8 * w + r];
        }
        __syncthreads();
        if (tid == 0) {
            __threadfence();
            int old = atomicAdd(&g_qc[g], 1);
            S->merge = (old == NQ - 1);
        }
        __syncthreads();
        if (S->merge) {
            __threadfence();
            if (tid < 64) {
                int kk = *kp; if (kk > 5) kk = 5;
                float best[6];
                #pragma unroll
                for (int i = 0; i < 6; i++) best[i] = 3.4e38f;
                for (int qq = 0; qq < NQ; qq++) {
                    #pragma unroll
                    for (int i = 0; i < 6; i++) {
                        float v = g_t6[g][qq][tid][i];
                        if (v < best[5]) {
                            best[5] = v;
                            #pragma unroll
                            for (int j2 = 5; j2 > 0; j2--)
                                if (best[j2] < best[j2 - 1]) {
                                    float tm = best[j2]; best[j2] = best[j2 - 1]; best[j2 - 1] = tm;
                                }
                        }
                    }
                }
                g_logrho[row0 + tid] = logf(fmaxf(best[kk], 1e-12f));
            }
            if (tid == 0) g_qc[g] = 0;   // reset for graph replay
        }
    } else {
        // ================= PREP (256 thr, 4 elems/thread) ================
        PrepS* P = (PrepS*)sm;
        const int col = bx - NBLK_KNN;
        float s1 = 0.f, s2 = 0.f;
        #pragma unroll
        for (int t = 0; t < 4; t++) {
            float v = act[(tid + 256 * t) * N_DIM + col];
            P->u[tid + 256 * t] = v;
            s1 += v;
            s2 += v * v;
        }
        P->red[tid] = s1; __syncthreads();
        for (int st = 128; st > 0; st >>= 1) {
            if (tid < st) P->red[tid] += P->red[tid + st];
            __syncthreads();
        }
        float tot1 = P->red[0]; __syncthreads();
        P->red[tid] = s2; __syncthreads();
        for (int st = 128; st > 0; st >>= 1) {
            if (tid < st) P->red[tid] += P->red[tid + st];
            __syncthreads();
        }
        if (tid == 0) {
            const float Bf = (float)B_ROWS;
            float mean = tot1 / Bf;
            float var  = (P->red[0] - Bf * mean * mean) / (Bf - 1.0f);
            float stdv = sqrtf(fmaxf(var, 0.f));
            float h    = fmaxf(1.06f * stdv * 0.25f, 1e-4f);
            float ih   = 1.0f / h;
            g_invh[col] = ih;
            P->scale    = ih;
        }
        __syncthreads();
        const float sc = P->scale;
        #pragma unroll
        for (int t = 0; t < 4; t++)
            P->u[tid + 256 * t] *= sc;

        for (int kk2 = 2; kk2 <= B_ROWS; kk2 <<= 1) {
            for (int jj = kk2 >> 1; jj > 0; jj >>= 1) {
                __syncthreads();
                #pragma unroll
                for (int t = 0; t < 4; t++) {
                    int i = tid + 256 * t;
                    int ixj = i ^ jj;
                    if (ixj > i) {
                        bool up = ((i & kk2) == 0);
                        float a = P->u[i], b = P->u[ixj];
                        if ((a > b) == up) { P->u[i] = b; P->u[ixj] = a; }
                    }
                }
            }
        }
        __syncthreads();
        #pragma unroll
        for (int t = 0; t < 4; t++)
            g_cols[col * B_ROWS + tid + 256 * t] = P->u[tid + 256 * t];
    }
}

// ---------------------------------------------------------------------------
// Kernel 2: KDE — 4 chunks/block {q,q+8,q+16,q+24}, 2 warps per chunk.
// grid = 512 (col*8+q), block = 256. Hermite moments + reflections split.
// ---------------------------------------------------------------------------
__global__ __launch_bounds__(256)
void k2(const int* __restrict__ kp, float* __restrict__ out) {
    __shared__ __align__(16) float u[B_ROWS];
    __shared__ float msum[4][2][NMOM];
    __shared__ float rsum[4][2][32];
    __shared__ int   bnd[4][4];
    __shared__ double dred[256];
    __shared__ int   sdone;

    const int tid  = threadIdx.x;
    const int lane = tid & 31;
    const int w    = tid >> 5;
    const int cidx = w >> 1;          // chunk index within block (0..3)
    const int sub  = w & 1;           // warp pair member
    const int col  = blockIdx.x >> 3;
    const int q    = blockIdx.x & 7;
    const int chunk = q + 8 * cidx;

    ((float4*)u)[tid] = ((const float4*)(g_cols + col * B_ROWS))[tid];
    __syncthreads();

    const float ih = g_invh[col];
    const float c2 = 2.0f * ih;
    const int   q0 = chunk * 32;
    const float x  = u[q0 + lane];
    const float cen = 0.5f * (u[q0] + u[q0 + 31]);

    if (tid < 16) {
        int ci = tid >> 2, i2 = tid & 3;
        int ch = q + 8 * ci;
        float xmn = u[ch * 32], xmx = u[ch * 32 + 31];
        float tgt = (i2 == 0) ? xmn - TS : (i2 == 1) ? xmx + TS
                  : (i2 == 2) ? TS - xmn : c2 - TS - xmx;
        int pos = 0;
        #pragma unroll
        for (int step = 1024; step; step >>= 1) {
            int np = pos + step;
            if (np <= B_ROWS && u[np - 1] < tgt) pos = np;
        }
        bnd[ci][i2] = pos;
    }
    __syncthreads();
    const int a0 = bnd[cidx][0], b0 = bnd[cidx][1];
    const int bL = bnd[cidx][2], aR = bnd[cidx][3];

    // ---- Hermite moments: warp-pair splits window by 64-stride ----
    {
        constexpr float INV[NMOM] = {0.f, 1.f, 0.5f, 0.33333334f, 0.25f, 0.2f,
            0.16666667f, 0.14285715f, 0.125f, 0.11111111f, 0.1f};
        float M[NMOM];
        #pragma unroll
        for (int n = 0; n < NMOM; n++) M[n] = 0.f;
        for (int j = a0 + sub * 32 + lane; j < b0; j += 64) {
            float uj = u[j] - cen;
            float wg = ex2(K2C * uj * uj);
            float bp = wg, bc = wg * uj;
            M[0] += bp;
            M[1] += bc;
            #pragma unroll
            for (int n = 1; n < NMOM - 1; n++) {
                float bn = fmaf(uj, bc, -bp) * INV[n + 1];
                M[n + 1] += bn;
                bp = bc; bc = bn;
            }
        }
        #pragma unroll
        for (int n = 0; n < NMOM; n++) {
            #pragma unroll
            for (int off = 16; off; off >>= 1)
                M[n] += __shfl_xor_sync(0xffffffffu, M[n], off);
        }
        if (lane == 0) {
            #pragma unroll
            for (int n = 0; n < NMOM; n++) msum[cidx][sub][n] = M[n];
        }
    }

    // ---- reflections: warp pair splits j by stride 2 ----
    {
        float f = 0.f;
        for (int j = sub; j < bL; j += 2) {
            float s = x + u[j];
            f += ex2(K2C * s * s);
        }
        const float xc = x - c2;
        for (int j = aR + sub; j < B_ROWS; j += 2) {
            float s = xc + u[j];
            f += ex2(K2C * s * s);
        }
        rsum[cidx][sub][lane] = f;
    }
    __syncthreads();

    if (sub == 0) {
        float Mn[NMOM];
        #pragma unroll
        for (int n = 0; n < NMOM; n++)
            Mn[n] = msum[cidx][0][n] + msum[cidx][1][n];
        const float delta = x - cen;
        float f = Mn[NMOM - 1];
        #pragma unroll
        for (int n = NMOM - 2; n >= 0; n--)
            f = fmaf(f, delta, Mn[n]);
        f += rsum[cidx][0][lane] + rsum[cidx][1][lane];

        const float Bf = (float)B_ROWS;
        const float scale = ih * (1.0f / (Bf * 2.5066282746310002f));
        float l = logf(f * scale + 1e-8f);
        #pragma unroll
        for (int off = 16; off; off >>= 1)
            l += __shfl_xor_sync(0xffffffffu, l, off);
        if (lane == 0)
            g_partials[col * QCH + chunk] = l;
    }

    // ---- completion counter + final assembly ----
    __syncthreads();
    if (tid == 0) {
        __threadfence();
        unsigned p = atomicAdd(&g_done, 1);
        sdone = (p == NBLK_K2 - 1);
    }
    __syncthreads();
    if (!sdone) return;
    __threadfence();

    if (tid < N_DIM) {
        float t = 0.f;
        #pragma unroll
        for (int c = 0; c < QCH; c++)
            t += g_partials[tid * QCH + c];
        out[1 + tid] = -t / (float)B_ROWS;
    }
    {
        double s = 0.0;
        for (int i = tid; i < B_ROWS; i += 256) s += (double)g_logrho[i];
        dred[tid] = s; __syncthreads();
        for (int st = 128; st > 0; st >>= 1) {
            if (tid < st) dred[tid] += dred[tid + st];
            __syncthreads();
        }
        if (tid == 0) {
            const int k = *kp;
            const double EULER    = 0.5772156649015328606;
            const double DG_B     = 6.9309834448765934;     // psi(1024)
            const double LGAMMA33 = 81.55795945611503558;   // lgamma(64/2+1)
            const double LOG_PI   = 1.1447298858494001741;
            const double INV_LN2  = 1.4426950408889634074;
            double dg_k = -EULER;
            for (int i = 1; i < k; i++) dg_k += 1.0 / (double)i;
            double log_c_d = 0.5 * (double)N_DIM * LOG_PI - LGAMMA33;
            double mean_lr = dred[0] / (double)B_ROWS;
            double h_nats = -dg_k + DG_B + log_c_d + (double)N_DIM * 0.5 * mean_lr;
            out[0] = (float)(h_nats * INV_LN2);
        }
    }
}

// ---------------------------------------------------------------------------
extern "C" void kernel_launch(void* const* d_in, const int* in_sizes, int n_in,
                              void* d_out, int out_size) {
    const float* act = (const float*)d_in[0];
    const int*   kp  = (const int*)d_in[1];
    float* out = (float*)d_out;
    (void)in_sizes; (void)n_in; (void)out_size;

    k1<<<NBLK_KNN + N_DIM, 256>>>(act, kp);
    k2<<<NBLK_K2, 256>>>(kp, out);
}

// round 14
// speedup vs baseline: 1.1772x; 1.1772x over previous
#include <cuda_runtime.h>
#include <math.h>

#define N_DIM    64
#define B_ROWS   1024
#define QCH      32
#define NGRP     32                // knn row-groups of 32
#define NQ       4                 // j-quarters (256 js each)
#define NBLK_KNN (NGRP * NQ)       // 128
#define NBLK_K2  512               // 64 cols x 8; 4 chunks x 2 warps per block
#define TS       3.5f              // truncation radius, h-units
#define K2C      (-0.72134752f)    // -0.5*log2(e)
#define NMOM     11                // Hermite terms 0..10

// Scratch (device globals — no allocation allowed)
__device__ float g_logrho[B_ROWS];
__device__ float g_cols[N_DIM * B_ROWS];   // sorted columns, scaled by 1/h
__device__ float g_invh[N_DIM];
__device__ float g_partials[N_DIM * QCH];
__device__ float g_t6[NGRP][NQ][32][6];
__device__ int   g_qc[NGRP];               // self-resetting quarter counters
__device__ int   g_colc[N_DIM];            // per-column completion (8 each)
__device__ int   g_done;                   // master counter (64 contenders)

__device__ __forceinline__ float ex2(float x) {
    float r;
    asm("ex2.approx.ftz.f32 %0, %1;" : "=f"(r) : "f"(x));
    return r;
}

// ---------------------------------------------------------------------------
// Kernel 1: knn (blocks 0..127) + prep (blocks 128..191), 256 threads.
// knn block: 32 rows (4/warp), 256 js (2 tiles of 128); fused shuffle norms.
// ---------------------------------------------------------------------------
struct KnnS {
    float tile[128][68];   // stride 68: conflict-free LDS.128
    float xq[32][64];
    float jn[128];
    float qn[32];
    int   merge;
};
struct PrepS {
    float u[B_ROWS];
    float red[256];
    float scale;
};

__global__ __launch_bounds__(256)
void k1(const float* __restrict__ act, const int* __restrict__ kp) {
    __shared__ __align__(16) char sm[sizeof(KnnS) > sizeof(PrepS) ? sizeof(KnnS) : sizeof(PrepS)];
    const int tid = threadIdx.x;
    const int bx  = blockIdx.x;

    if (bx < NBLK_KNN) {
        KnnS* S = (KnnS*)sm;
        const int g = bx >> 2, q = bx & 3;
        const int row0 = g * 32, jbase = q * 256;
        const int lane = tid & 31, w = tid >> 5;

        // 32 query rows + norms (half-warp shuffle reduce)
        {
            const float4* qsrc = (const float4*)(act + row0 * N_DIM);
            #pragma unroll
            for (int t = 0; t < 2; t++) {
                int fi = tid + t * 256;
                float4 v = qsrc[fi];
                ((float4*)S->xq)[fi] = v;
                float s = v.x * v.x + v.y * v.y + v.z * v.z + v.w * v.w;
                s += __shfl_down_sync(0xffffffffu, s, 8, 16);
                s += __shfl_down_sync(0xffffffffu, s, 4, 16);
                s += __shfl_down_sync(0xffffffffu, s, 2, 16);
                s += __shfl_down_sync(0xffffffffu, s, 1, 16);
                if ((lane & 15) == 0) S->qn[fi >> 4] = s;
            }
        }

        float m[4][6];
        #pragma unroll
        for (int r = 0; r < 4; r++)
            #pragma unroll
            for (int i = 0; i < 6; i++) m[r][i] = 3.4e38f;

        for (int t = 0; t < 2; t++) {
            __syncthreads();
            // 128-row tile + fused norms
            const float4* gsrc = (const float4*)(act + (jbase + t * 128) * N_DIM);
            #pragma unroll
            for (int it = 0; it < 8; it++) {
                int fi = tid + it * 256;
                float4 v = gsrc[fi];
                *(float4*)&S->tile[fi >> 4][(fi & 15) * 4] = v;
                float s = v.x * v.x + v.y * v.y + v.z * v.z + v.w * v.w;
                s += __shfl_down_sync(0xffffffffu, s, 8, 16);
                s += __shfl_down_sync(0xffffffffu, s, 4, 16);
                s += __shfl_down_sync(0xffffffffu, s, 2, 16);
                s += __shfl_down_sync(0xffffffffu, s, 1, 16);
                if ((lane & 15) == 0) S->jn[fi >> 4] = s;
            }
            __syncthreads();

            float acc[4][4];
            #pragma unroll
            for (int r = 0; r < 4; r++)
                #pragma unroll
                for (int s = 0; s < 4; s++) acc[r][s] = 0.f;

            #pragma unroll
            for (int c = 0; c < 8; c++) {      // 8-dim chunks
                float4 qr[4][2];
                #pragma unroll
                for (int r = 0; r < 4; r++) {
                    qr[r][0] = *(const float4*)&S->xq[4 * w + r][c * 8];
                    qr[r][1] = *(const float4*)&S->xq[4 * w + r][c * 8 + 4];
                }
                #pragma unroll
                for (int s = 0; s < 4; s++) {
                    const int j = lane + 32 * s;
                    const float4 b0 = *(const float4*)&S->tile[j][c * 8];
                    const float4 b1 = *(const float4*)&S->tile[j][c * 8 + 4];
                    #pragma unroll
                    for (int r = 0; r < 4; r++) {
                        float a = acc[r][s];
                        a = fmaf(qr[r][0].x, b0.x, a);
                        a = fmaf(qr[r][0].y, b0.y, a);
                        a = fmaf(qr[r][0].z, b0.z, a);
                        a = fmaf(qr[r][0].w, b0.w, a);
                        a = fmaf(qr[r][1].x, b1.x, a);
                        a = fmaf(qr[r][1].y, b1.y, a);
                        a = fmaf(qr[r][1].z, b1.z, a);
                        a = fmaf(qr[r][1].w, b1.w, a);
                        acc[r][s] = a;
                    }
                }
            }
            // candidates ranked by jn - 2*dot (qn constant per row)
            #pragma unroll
            for (int s = 0; s < 4; s++) {
                const float nj = S->jn[lane + 32 * s];
                #pragma unroll
                for (int r = 0; r < 4; r++) {
                    float v = fmaf(acc[r][s], -2.f, nj);
                    if (v < m[r][5]) {
                        m[r][5] = v;
                        #pragma unroll
                        for (int i = 5; i > 0; i--)
                            if (m[r][i] < m[r][i - 1]) {
                                float tm = m[r][i]; m[r][i] = m[r][i - 1]; m[r][i - 1] = tm;
                            }
                    }
                }
            }
        }

        // per-row: extract top-6 over lanes, add qn, store
        #pragma unroll
        for (int r = 0; r < 4; r++) {
            float l0 = m[r][0], l1 = m[r][1], l2 = m[r][2];
            float l3 = m[r][3], l4 = m[r][4], l5 = m[r][5];
            float keep = 3.4e38f;
            #pragma unroll
            for (int i = 0; i < 6; i++) {
                float mv = l0;
                #pragma unroll
                for (int off = 16; off; off >>= 1)
                    mv = fminf(mv, __shfl_xor_sync(0xffffffffu, mv, off));
                if (lane == i) keep = mv;
                unsigned msk = __ballot_sync(0xffffffffu, l0 == mv);
                if (lane == (__ffs(msk) - 1)) {
                    l0 = l1; l1 = l2; l2 = l3; l3 = l4; l4 = l5; l5 = 3.4e38f;
                }
            }
            if (lane < 6)
                g_t6[g][q][4 * w + r][lane] = keep + S->qn[4 * w + r];
        }
        __syncthreads();
        if (tid == 0) {
            __threadfence();
            int old = atomicAdd(&g_qc[g], 1);
            S->merge = (old == NQ - 1);
        }
        __syncthreads();
        if (S->merge) {
            __threadfence();
            if (tid < 32) {
                int kk = *kp; if (kk > 5) kk = 5;
                float best[6];
                #pragma unroll
                for (int i = 0; i < 6; i++) best[i] = 3.4e38f;
                #pragma unroll
                for (int qq = 0; qq < NQ; qq++) {
                    #pragma unroll
                    for (int i = 0; i < 6; i++) {
                        float v = g_t6[g][qq][tid][i];
                        if (v < best[5]) {
                            best[5] = v;
                            #pragma unroll
                            for (int j2 = 5; j2 > 0; j2--)
                                if (best[j2] < best[j2 - 1]) {
                                    float tm = best[j2]; best[j2] = best[j2 - 1]; best[j2 - 1] = tm;
                                }
                        }
                    }
                }
                g_logrho[row0 + tid] = logf(fmaxf(best[kk], 1e-12f));
            }
            if (tid == 0) g_qc[g] = 0;   // reset for graph replay
        }
    } else {
        // ================= PREP (256 thr, 4 elems/thread) ================
        PrepS* P = (PrepS*)sm;
        const int col = bx - NBLK_KNN;
        float s1 = 0.f, s2 = 0.f;
        #pragma unroll
        for (int t = 0; t < 4; t++) {
            float v = act[(tid + 256 * t) * N_DIM + col];
            P->u[tid + 256 * t] = v;
            s1 += v;
            s2 += v * v;
        }
        P->red[tid] = s1; __syncthreads();
        for (int st = 128; st > 0; st >>= 1) {
            if (tid < st) P->red[tid] += P->red[tid + st];
            __syncthreads();
        }
        float tot1 = P->red[0]; __syncthreads();
        P->red[tid] = s2; __syncthreads();
        for (int st = 128; st > 0; st >>= 1) {
            if (tid < st) P->red[tid] += P->red[tid + st];
            __syncthreads();
        }
        if (tid == 0) {
            const float Bf = (float)B_ROWS;
            float mean = tot1 / Bf;
            float var  = (P->red[0] - Bf * mean * mean) / (Bf - 1.0f);
            float stdv = sqrtf(fmaxf(var, 0.f));
            float h    = fmaxf(1.06f * stdv * 0.25f, 1e-4f);
            float ih   = 1.0f / h;
            g_invh[col] = ih;
            P->scale    = ih;
        }
        __syncthreads();
        const float sc = P->scale;
        #pragma unroll
        for (int t = 0; t < 4; t++)
            P->u[tid + 256 * t] *= sc;

        for (int kk2 = 2; kk2 <= B_ROWS; kk2 <<= 1) {
            for (int jj = kk2 >> 1; jj > 0; jj >>= 1) {
                __syncthreads();
                #pragma unroll
                for (int t = 0; t < 4; t++) {
                    int i = tid + 256 * t;
                    int ixj = i ^ jj;
                    if (ixj > i) {
                        bool up = ((i & kk2) == 0);
                        float a = P->u[i], b = P->u[ixj];
                        if ((a > b) == up) { P->u[i] = b; P->u[ixj] = a; }
                    }
                }
            }
        }
        __syncthreads();
        #pragma unroll
        for (int t = 0; t < 4; t++)
            g_cols[col * B_ROWS + tid + 256 * t] = P->u[tid + 256 * t];
    }
}

// ---------------------------------------------------------------------------
// Kernel 2: KDE — 4 chunks/block {q,q+8,q+16,q+24}, 2 warps per chunk.
// grid = 512 (col*8+q), block = 256. Hierarchical completion: per-column
// counter (8 contenders) -> column winner writes out[1+col] -> master (64).
// ---------------------------------------------------------------------------
__global__ __launch_bounds__(256)
void k2(const int* __restrict__ kp, float* __restrict__ out) {
    __shared__ __align__(16) float u[B_ROWS];
    __shared__ float msum[4][2][NMOM];
    __shared__ float rsum[4][2][32];
    __shared__ int   bnd[4][4];
    __shared__ double dred[256];
    __shared__ int   s_col_last, s_master;

    const int tid  = threadIdx.x;
    const int lane = tid & 31;
    const int w    = tid >> 5;
    const int cidx = w >> 1;          // chunk index within block (0..3)
    const int sub  = w & 1;           // warp pair member
    const int col  = blockIdx.x >> 3;
    const int q    = blockIdx.x & 7;
    const int chunk = q + 8 * cidx;

    ((float4*)u)[tid] = ((const float4*)(g_cols + col * B_ROWS))[tid];
    __syncthreads();

    const float ih = g_invh[col];
    const float c2 = 2.0f * ih;
    const int   q0 = chunk * 32;
    const float x  = u[q0 + lane];
    const float cen = 0.5f * (u[q0] + u[q0 + 31]);

    if (tid < 16) {
        int ci = tid >> 2, i2 = tid & 3;
        int ch = q + 8 * ci;
        float xmn = u[ch * 32], xmx = u[ch * 32 + 31];
        float tgt = (i2 == 0) ? xmn - TS : (i2 == 1) ? xmx + TS
                  : (i2 == 2) ? TS - xmn : c2 - TS - xmx;
        int pos = 0;
        #pragma unroll
        for (int step = 1024; step; step >>= 1) {
            int np = pos + step;
            if (np <= B_ROWS && u[np - 1] < tgt) pos = np;
        }
        bnd[ci][i2] = pos;
    }
    __syncthreads();
    const int a0 = bnd[cidx][0], b0 = bnd[cidx][1];
    const int bL = bnd[cidx][2], aR = bnd[cidx][3];

    // ---- Hermite moments: warp-pair splits window by 64-stride ----
    {
        constexpr float INV[NMOM] = {0.f, 1.f, 0.5f, 0.33333334f, 0.25f, 0.2f,
            0.16666667f, 0.14285715f, 0.125f, 0.11111111f, 0.1f};
        float M[NMOM];
        #pragma unroll
        for (int n = 0; n < NMOM; n++) M[n] = 0.f;
        for (int j = a0 + sub * 32 + lane; j < b0; j += 64) {
            float uj = u[j] - cen;
            float wg = ex2(K2C * uj * uj);
            float bp = wg, bc = wg * uj;
            M[0] += bp;
            M[1] += bc;
            #pragma unroll
            for (int n = 1; n < NMOM - 1; n++) {
                float bn = fmaf(uj, bc, -bp) * INV[n + 1];
                M[n + 1] += bn;
                bp = bc; bc = bn;
            }
        }
        #pragma unroll
        for (int n = 0; n < NMOM; n++) {
            #pragma unroll
            for (int off = 16; off; off >>= 1)
                M[n] += __shfl_xor_sync(0xffffffffu, M[n], off);
        }
        if (lane == 0) {
            #pragma unroll
            for (int n = 0; n < NMOM; n++) msum[cidx][sub][n] = M[n];
        }
    }

    // ---- reflections: warp pair splits j by stride 2 ----
    {
        float f = 0.f;
        for (int j = sub; j < bL; j += 2) {
            float s = x + u[j];
            f += ex2(K2C * s * s);
        }
        const float xc = x - c2;
        for (int j = aR + sub; j < B_ROWS; j += 2) {
            float s = xc + u[j];
            f += ex2(K2C * s * s);
        }
        rsum[cidx][sub][lane] = f;
    }
    __syncthreads();

    if (sub == 0) {
        float Mn[NMOM];
        #pragma unroll
        for (int n = 0; n < NMOM; n++)
            Mn[n] = msum[cidx][0][n] + msum[cidx][1][n];
        const float delta = x - cen;
        float f = Mn[NMOM - 1];
        #pragma unroll
        for (int n = NMOM - 2; n >= 0; n--)
            f = fmaf(f, delta, Mn[n]);
        f += rsum[cidx][0][lane] + rsum[cidx][1][lane];

        const float Bf = (float)B_ROWS;
        const float scale = ih * (1.0f / (Bf * 2.5066282746310002f));
        float l = logf(f * scale + 1e-8f);
        #pragma unroll
        for (int off = 16; off; off >>= 1)
            l += __shfl_xor_sync(0xffffffffu, l, off);
        if (lane == 0)
            g_partials[col * QCH + chunk] = l;
    }

    // ---- hierarchical completion ----
    __syncthreads();
    if (tid == 0) {
        __threadfence();
        int old = atomicAdd(&g_colc[col], 1);
        s_col_last = (old == 7);
    }
    __syncthreads();
    if (!s_col_last) return;
    __threadfence();

    // column winner: assemble this column's marginal entropy
    if (tid < 32) {
        float t = g_partials[col * QCH + tid];
        #pragma unroll
        for (int off = 16; off; off >>= 1)
            t += __shfl_xor_sync(0xffffffffu, t, off);
        if (tid == 0) {
            out[1 + col] = -t / (float)B_ROWS;
            g_colc[col] = 0;   // reset for graph replay
        }
    }
    __syncthreads();
    if (tid == 0) {
        __threadfence();
        int old = atomicAdd(&g_done, 1);
        s_master = (old == N_DIM - 1);
    }
    __syncthreads();
    if (!s_master) return;
    __threadfence();

    // master: fp64 joint entropy
    {
        double s = 0.0;
        for (int i = tid; i < B_ROWS; i += 256) s += (double)g_logrho[i];
        dred[tid] = s; __syncthreads();
        for (int st = 128; st > 0; st >>= 1) {
            if (tid < st) dred[tid] += dred[tid + st];
            __syncthreads();
        }
        if (tid == 0) {
            const int k = *kp;
            const double EULER    = 0.5772156649015328606;
            const double DG_B     = 6.9309834448765934;     // psi(1024)
            const double LGAMMA33 = 81.55795945611503558;   // lgamma(64/2+1)
            const double LOG_PI   = 1.1447298858494001741;
            const double INV_LN2  = 1.4426950408889634074;
            double dg_k = -EULER;
            for (int i = 1; i < k; i++) dg_k += 1.0 / (double)i;
            double log_c_d = 0.5 * (double)N_DIM * LOG_PI - LGAMMA33;
            double mean_lr = dred[0] / (double)B_ROWS;
            double h_nats = -dg_k + DG_B + log_c_d + (double)N_DIM * 0.5 * mean_lr;
            out[0] = (float)(h_nats * INV_LN2);
            g_done = 0;   // reset for graph replay
        }
    }
}

// ---------------------------------------------------------------------------
extern "C" void kernel_launch(void* const* d_in, const int* in_sizes, int n_in,
                              void* d_out, int out_size) {
    const float* act = (const float*)d_in[0];
    const int*   kp  = (const int*)d_in[1];
    float* out = (float*)d_out;
    (void)in_sizes; (void)n_in; (void)out_size;

    k1<<<NBLK_KNN + N_DIM, 256>>>(act, kp);
    k2<<<NBLK_K2, 256>>>(kp, out);
}

// round 15
// speedup vs baseline: 1.2186x; 1.0352x over previous
#include <cuda_runtime.h>
#include <math.h>

#define N_DIM    64
#define B_ROWS   1024
#define QCH      32
#define NGRP     32                // knn row-groups of 32
#define NQ       4                 // j-quarters (256 js each)
#define NBLK_KNN (NGRP * NQ)       // 128
#define NBLK_K2  1024              // 64 cols x 16; 2 chunks x 4 warps per block
#define TS       3.5f              // truncation radius, h-units
#define K2C      (-0.72134752f)    // -0.5*log2(e)
#define NMOM     11                // Hermite terms 0..10

// Scratch (device globals — no allocation allowed)
__device__ float g_logrho[B_ROWS];
__device__ float g_cols[N_DIM * B_ROWS];   // sorted columns, scaled by 1/h
__device__ float g_invh[N_DIM];
__device__ float g_partials[N_DIM * QCH];
__device__ float g_t6[NGRP][NQ][32][6];
__device__ int   g_qc[NGRP];               // self-resetting quarter counters
__device__ int   g_colc[N_DIM];            // per-column completion (16 each)
__device__ int   g_done;                   // master counter (64 contenders)

__device__ __forceinline__ float ex2(float x) {
    float r;
    asm("ex2.approx.ftz.f32 %0, %1;" : "=f"(r) : "f"(x));
    return r;
}

// ---------------------------------------------------------------------------
// Kernel 1: knn (blocks 0..127) + prep (blocks 128..191), 256 threads.
// (unchanged from round 14 — best measured)
// ---------------------------------------------------------------------------
struct KnnS {
    float tile[128][68];   // stride 68: conflict-free LDS.128
    float xq[32][64];
    float jn[128];
    float qn[32];
    int   merge;
};
struct PrepS {
    float u[B_ROWS];
    float red[256];
    float scale;
};

__global__ __launch_bounds__(256)
void k1(const float* __restrict__ act, const int* __restrict__ kp) {
    __shared__ __align__(16) char sm[sizeof(KnnS) > sizeof(PrepS) ? sizeof(KnnS) : sizeof(PrepS)];
    const int tid = threadIdx.x;
    const int bx  = blockIdx.x;

    if (bx < NBLK_KNN) {
        KnnS* S = (KnnS*)sm;
        const int g = bx >> 2, q = bx & 3;
        const int row0 = g * 32, jbase = q * 256;
        const int lane = tid & 31, w = tid >> 5;

        // 32 query rows + norms (half-warp shuffle reduce)
        {
            const float4* qsrc = (const float4*)(act + row0 * N_DIM);
            #pragma unroll
            for (int t = 0; t < 2; t++) {
                int fi = tid + t * 256;
                float4 v = qsrc[fi];
                ((float4*)S->xq)[fi] = v;
                float s = v.x * v.x + v.y * v.y + v.z * v.z + v.w * v.w;
                s += __shfl_down_sync(0xffffffffu, s, 8, 16);
                s += __shfl_down_sync(0xffffffffu, s, 4, 16);
                s += __shfl_down_sync(0xffffffffu, s, 2, 16);
                s += __shfl_down_sync(0xffffffffu, s, 1, 16);
                if ((lane & 15) == 0) S->qn[fi >> 4] = s;
            }
        }

        float m[4][6];
        #pragma unroll
        for (int r = 0; r < 4; r++)
            #pragma unroll
            for (int i = 0; i < 6; i++) m[r][i] = 3.4e38f;

        for (int t = 0; t < 2; t++) {
            __syncthreads();
            const float4* gsrc = (const float4*)(act + (jbase + t * 128) * N_DIM);
            #pragma unroll
            for (int it = 0; it < 8; it++) {
                int fi = tid + it * 256;
                float4 v = gsrc[fi];
                *(float4*)&S->tile[fi >> 4][(fi & 15) * 4] = v;
                float s = v.x * v.x + v.y * v.y + v.z * v.z + v.w * v.w;
                s += __shfl_down_sync(0xffffffffu, s, 8, 16);
                s += __shfl_down_sync(0xffffffffu, s, 4, 16);
                s += __shfl_down_sync(0xffffffffu, s, 2, 16);
                s += __shfl_down_sync(0xffffffffu, s, 1, 16);
                if ((lane & 15) == 0) S->jn[fi >> 4] = s;
            }
            __syncthreads();

            float acc[4][4];
            #pragma unroll
            for (int r = 0; r < 4; r++)
                #pragma unroll
                for (int s = 0; s < 4; s++) acc[r][s] = 0.f;

            #pragma unroll
            for (int c = 0; c < 8; c++) {      // 8-dim chunks
                float4 qr[4][2];
                #pragma unroll
                for (int r = 0; r < 4; r++) {
                    qr[r][0] = *(const float4*)&S->xq[4 * w + r][c * 8];
                    qr[r][1] = *(const float4*)&S->xq[4 * w + r][c * 8 + 4];
                }
                #pragma unroll
                for (int s = 0; s < 4; s++) {
                    const int j = lane + 32 * s;
                    const float4 b0 = *(const float4*)&S->tile[j][c * 8];
                    const float4 b1 = *(const float4*)&S->tile[j][c * 8 + 4];
                    #pragma unroll
                    for (int r = 0; r < 4; r++) {
                        float a = acc[r][s];
                        a = fmaf(qr[r][0].x, b0.x, a);
                        a = fmaf(qr[r][0].y, b0.y, a);
                        a = fmaf(qr[r][0].z, b0.z, a);
                        a = fmaf(qr[r][0].w, b0.w, a);
                        a = fmaf(qr[r][1].x, b1.x, a);
                        a = fmaf(qr[r][1].y, b1.y, a);
                        a = fmaf(qr[r][1].z, b1.z, a);
                        a = fmaf(qr[r][1].w, b1.w, a);
                        acc[r][s] = a;
                    }
                }
            }
            #pragma unroll
            for (int s = 0; s < 4; s++) {
                const float nj = S->jn[lane + 32 * s];
                #pragma unroll
                for (int r = 0; r < 4; r++) {
                    float v = fmaf(acc[r][s], -2.f, nj);
                    if (v < m[r][5]) {
                        m[r][5] = v;
                        #pragma unroll
                        for (int i = 5; i > 0; i--)
                            if (m[r][i] < m[r][i - 1]) {
                                float tm = m[r][i]; m[r][i] = m[r][i - 1]; m[r][i - 1] = tm;
                            }
                    }
                }
            }
        }

        // per-row: extract top-6 over lanes, add qn, store
        #pragma unroll
        for (int r = 0; r < 4; r++) {
            float l0 = m[r][0], l1 = m[r][1], l2 = m[r][2];
            float l3 = m[r][3], l4 = m[r][4], l5 = m[r][5];
            float keep = 3.4e38f;
            #pragma unroll
            for (int i = 0; i < 6; i++) {
                float mv = l0;
                #pragma unroll
                for (int off = 16; off; off >>= 1)
                    mv = fminf(mv, __shfl_xor_sync(0xffffffffu, mv, off));
                if (lane == i) keep = mv;
                unsigned msk = __ballot_sync(0xffffffffu, l0 == mv);
                if (lane == (__ffs(msk) - 1)) {
                    l0 = l1; l1 = l2; l2 = l3; l3 = l4; l4 = l5; l5 = 3.4e38f;
                }
            }
            if (lane < 6)
                g_t6[g][q][4 * w + r][lane] = keep + S->qn[4 * w + r];
        }
        __syncthreads();
        if (tid == 0) {
            __threadfence();
            int old = atomicAdd(&g_qc[g], 1);
            S->merge = (old == NQ - 1);
        }
        __syncthreads();
        if (S->merge) {
            __threadfence();
            if (tid < 32) {
                int kk = *kp; if (kk > 5) kk = 5;
                float best[6];
                #pragma unroll
                for (int i = 0; i < 6; i++) best[i] = 3.4e38f;
                #pragma unroll
                for (int qq = 0; qq < NQ; qq++) {
                    #pragma unroll
                    for (int i = 0; i < 6; i++) {
                        float v = g_t6[g][qq][tid][i];
                        if (v < best[5]) {
                            best[5] = v;
                            #pragma unroll
                            for (int j2 = 5; j2 > 0; j2--)
                                if (best[j2] < best[j2 - 1]) {
                                    float tm = best[j2]; best[j2] = best[j2 - 1]; best[j2 - 1] = tm;
                                }
                        }
                    }
                }
                g_logrho[row0 + tid] = logf(fmaxf(best[kk], 1e-12f));
            }
            if (tid == 0) g_qc[g] = 0;   // reset for graph replay
        }
    } else {
        // ================= PREP (256 thr, 4 elems/thread) ================
        PrepS* P = (PrepS*)sm;
        const int col = bx - NBLK_KNN;
        float s1 = 0.f, s2 = 0.f;
        #pragma unroll
        for (int t = 0; t < 4; t++) {
            float v = act[(tid + 256 * t) * N_DIM + col];
            P->u[tid + 256 * t] = v;
            s1 += v;
            s2 += v * v;
        }
        P->red[tid] = s1; __syncthreads();
        for (int st = 128; st > 0; st >>= 1) {
            if (tid < st) P->red[tid] += P->red[tid + st];
            __syncthreads();
        }
        float tot1 = P->red[0]; __syncthreads();
        P->red[tid] = s2; __syncthreads();
        for (int st = 128; st > 0; st >>= 1) {
            if (tid < st) P->red[tid] += P->red[tid + st];
            __syncthreads();
        }
        if (tid == 0) {
            const float Bf = (float)B_ROWS;
            float mean = tot1 / Bf;
            float var  = (P->red[0] - Bf * mean * mean) / (Bf - 1.0f);
            float stdv = sqrtf(fmaxf(var, 0.f));
            float h    = fmaxf(1.06f * stdv * 0.25f, 1e-4f);
            float ih   = 1.0f / h;
            g_invh[col] = ih;
            P->scale    = ih;
        }
        __syncthreads();
        const float sc = P->scale;
        #pragma unroll
        for (int t = 0; t < 4; t++)
            P->u[tid + 256 * t] *= sc;

        for (int kk2 = 2; kk2 <= B_ROWS; kk2 <<= 1) {
            for (int jj = kk2 >> 1; jj > 0; jj >>= 1) {
                __syncthreads();
                #pragma unroll
                for (int t = 0; t < 4; t++) {
                    int i = tid + 256 * t;
                    int ixj = i ^ jj;
                    if (ixj > i) {
                        bool up = ((i & kk2) == 0);
                        float a = P->u[i], b = P->u[ixj];
                        if ((a > b) == up) { P->u[i] = b; P->u[ixj] = a; }
                    }
                }
            }
        }
        __syncthreads();
        #pragma unroll
        for (int t = 0; t < 4; t++)
            g_cols[col * B_ROWS + tid + 256 * t] = P->u[tid + 256 * t];
    }
}

// ---------------------------------------------------------------------------
// Kernel 2: KDE — reflections folded into Hermite moments; per-query cost is
// one Horner. grid = 1024 (col*16+cp); block = 256: chunks cp (warps 0-3)
// and 31-cp (warps 4-7), 4 warps of moment accumulation each.
// ---------------------------------------------------------------------------
__global__ __launch_bounds__(256)
void k2(const int* __restrict__ kp, float* __restrict__ out) {
    __shared__ __align__(16) float u[B_ROWS];
    __shared__ float msum[2][4][NMOM];
    __shared__ int   bnd[2][4];
    __shared__ double dred[256];
    __shared__ int   s_col_last, s_master;

    const int tid  = threadIdx.x;
    const int lane = tid & 31;
    const int w    = tid >> 5;
    const int half = w >> 2;
    const int wl   = w & 3;
    const int col  = blockIdx.x >> 4;
    const int cp   = blockIdx.x & 15;
    const int chunk = half ? (31 - cp) : cp;

    ((float4*)u)[tid] = ((const float4*)(g_cols + col * B_ROWS))[tid];
    __syncthreads();

    const float ih = g_invh[col];
    const float c2 = 2.0f * ih;
    const int   q0 = chunk * 32;
    const float x  = u[q0 + lane];
    const float cen = 0.5f * (u[q0] + u[q0 + 31]);

    if (tid < 8) {
        int h2 = tid >> 2, i2 = tid & 3;
        int ch = h2 ? (31 - cp) : cp;
        float xmn = u[ch * 32], xmx = u[ch * 32 + 31];
        float tgt = (i2 == 0) ? xmn - TS : (i2 == 1) ? xmx + TS
                  : (i2 == 2) ? TS - xmn : c2 - TS - xmx;
        int pos = 0;
        #pragma unroll
        for (int step = 1024; step; step >>= 1) {
            int np = pos + step;
            if (np <= B_ROWS && u[np - 1] < tgt) pos = np;
        }
        bnd[h2][i2] = pos;
    }
    __syncthreads();
    const int a0 = bnd[half][0], b0 = bnd[half][1];
    const int bL = bnd[half][2], aR = bnd[half][3];

    // ---- Hermite moments over main + mirrored windows (4 warps) ----
    {
        constexpr float INV[NMOM] = {0.f, 1.f, 0.5f, 0.33333334f, 0.25f, 0.2f,
            0.16666667f, 0.14285715f, 0.125f, 0.11111111f, 0.1f};
        float M[NMOM];
        #pragma unroll
        for (int n = 0; n < NMOM; n++) M[n] = 0.f;
        const int t128 = wl * 32 + lane;

        #define HSTEP(arg) do {                                   \
            float uj_ = (arg);                                    \
            float wg_ = ex2(K2C * uj_ * uj_);                     \
            float bp_ = wg_, bc_ = wg_ * uj_;                     \
            M[0] += bp_; M[1] += bc_;                             \
            _Pragma("unroll")                                     \
            for (int n_ = 1; n_ < NMOM - 1; n_++) {               \
                float bn_ = fmaf(uj_, bc_, -bp_) * INV[n_ + 1];   \
                M[n_ + 1] += bn_; bp_ = bc_; bc_ = bn_;           \
            }                                                     \
        } while (0)

        for (int j = a0 + t128; j < b0; j += 128) HSTEP(u[j] - cen);
        for (int j = t128; j < bL; j += 128)      HSTEP(-u[j] - cen);
        for (int j = aR + t128; j < B_ROWS; j += 128) HSTEP(c2 - u[j] - cen);
        #undef HSTEP

        #pragma unroll
        for (int n = 0; n < NMOM; n++) {
            #pragma unroll
            for (int off = 16; off; off >>= 1)
                M[n] += __shfl_xor_sync(0xffffffffu, M[n], off);
        }
        if (lane == 0) {
            #pragma unroll
            for (int n = 0; n < NMOM; n++) msum[half][wl][n] = M[n];
        }
    }
    __syncthreads();

    // ---- per-query Horner only (warp wl==0 of each half) ----
    if (wl == 0) {
        float Mn[NMOM];
        #pragma unroll
        for (int n = 0; n < NMOM; n++)
            Mn[n] = (msum[half][0][n] + msum[half][1][n])
                  + (msum[half][2][n] + msum[half][3][n]);
        const float delta = x - cen;
        float f = Mn[NMOM - 1];
        #pragma unroll
        for (int n = NMOM - 2; n >= 0; n--)
            f = fmaf(f, delta, Mn[n]);

        const float Bf = (float)B_ROWS;
        const float scale = ih * (1.0f / (Bf * 2.5066282746310002f));
        float l = logf(f * scale + 1e-8f);
        #pragma unroll
        for (int off = 16; off; off >>= 1)
            l += __shfl_xor_sync(0xffffffffu, l, off);
        if (lane == 0)
            g_partials[col * QCH + chunk] = l;
    }

    // ---- hierarchical completion ----
    __syncthreads();
    if (tid == 0) {
        __threadfence();
        int old = atomicAdd(&g_colc[col], 1);
        s_col_last = (old == 15);
    }
    __syncthreads();
    if (!s_col_last) return;
    __threadfence();

    // column winner: assemble this column's marginal entropy
    if (tid < 32) {
        float t = g_partials[col * QCH + tid];
        #pragma unroll
        for (int off = 16; off; off >>= 1)
            t += __shfl_xor_sync(0xffffffffu, t, off);
        if (tid == 0) {
            out[1 + col] = -t / (float)B_ROWS;
            g_colc[col] = 0;   // reset for graph replay
        }
    }
    __syncthreads();
    if (tid == 0) {
        __threadfence();
        int old = atomicAdd(&g_done, 1);
        s_master = (old == N_DIM - 1);
    }
    __syncthreads();
    if (!s_master) return;
    __threadfence();

    // master: fp64 joint entropy
    {
        double s = 0.0;
        for (int i = tid; i < B_ROWS; i += 256) s += (double)g_logrho[i];
        dred[tid] = s; __syncthreads();
        for (int st = 128; st > 0; st >>= 1) {
            if (tid < st) dred[tid] += dred[tid + st];
            __syncthreads();
        }
        if (tid == 0) {
            const int k = *kp;
            const double EULER    = 0.5772156649015328606;
            const double DG_B     = 6.9309834448765934;     // psi(1024)
            const double LGAMMA33 = 81.55795945611503558;   // lgamma(64/2+1)
            const double LOG_PI   = 1.1447298858494001741;
            const double INV_LN2  = 1.4426950408889634074;
            double dg_k = -EULER;
            for (int i = 1; i < k; i++) dg_k += 1.0 / (double)i;
            double log_c_d = 0.5 * (double)N_DIM * LOG_PI - LGAMMA33;
            double mean_lr = dred[0] / (double)B_ROWS;
            double h_nats = -dg_k + DG_B + log_c_d + (double)N_DIM * 0.5 * mean_lr;
            out[0] = (float)(h_nats * INV_LN2);
            g_done = 0;   // reset for graph replay
        }
    }
}

// ---------------------------------------------------------------------------
extern "C" void kernel_launch(void* const* d_in, const int* in_sizes, int n_in,
                              void* d_out, int out_size) {
    const float* act = (const float*)d_in[0];
    const int*   kp  = (const int*)d_in[1];
    float* out = (float*)d_out;
    (void)in_sizes; (void)n_in; (void)out_size;

    k1<<<NBLK_KNN + N_DIM, 256>>>(act, kp);
    k2<<<NBLK_K2, 256>>>(kp, out);
}

// round 16
// speedup vs baseline: 1.3285x; 1.0902x over previous
#include <cuda_runtime.h>
#include <math.h>

#define N_DIM    64
#define B_ROWS   1024
#define QCH2     16                // kde chunks of 64 queries
#define NGRP     32                // knn row-groups of 32
#define NQ       4                 // j-quarters (256 js each)
#define NBLK_KNN (NGRP * NQ)       // 128
#define NBLK_K2  512               // 64 cols x 8; 2 chunks x 4 warps per block
#define TS       3.5f              // truncation radius, h-units
#define K2C      (-0.72134752f)    // -0.5*log2(e)
#define NMOM     10                // Hermite terms 0..9

// Scratch (device globals — no allocation allowed)
__device__ float g_logrho[B_ROWS];
__device__ float g_cols[N_DIM * B_ROWS];   // sorted columns, scaled by 1/h
__device__ float g_invh[N_DIM];
__device__ float g_partials[N_DIM * QCH2];
__device__ float g_t6[NGRP][NQ][32][6];
__device__ int   g_qc[NGRP];               // self-resetting quarter counters
__device__ int   g_colc[N_DIM];            // per-column completion (8 each)
__device__ int   g_done;                   // master counter (64 contenders)

__device__ __forceinline__ float ex2(float x) {
    float r;
    asm("ex2.approx.ftz.f32 %0, %1;" : "=f"(r) : "f"(x));
    return r;
}

// ---------------------------------------------------------------------------
// Kernel 1: knn (blocks 0..127) + prep (blocks 128..191), 256 threads.
// (unchanged — best measured)
// ---------------------------------------------------------------------------
struct KnnS {
    float tile[128][68];   // stride 68: conflict-free LDS.128
    float xq[32][64];
    float jn[128];
    float qn[32];
    int   merge;
};
struct PrepS {
    float u[B_ROWS];
    float red[256];
    float scale;
};

__global__ __launch_bounds__(256)
void k1(const float* __restrict__ act, const int* __restrict__ kp) {
    __shared__ __align__(16) char sm[sizeof(KnnS) > sizeof(PrepS) ? sizeof(KnnS) : sizeof(PrepS)];
    const int tid = threadIdx.x;
    const int bx  = blockIdx.x;

    if (bx < NBLK_KNN) {
        KnnS* S = (KnnS*)sm;
        const int g = bx >> 2, q = bx & 3;
        const int row0 = g * 32, jbase = q * 256;
        const int lane = tid & 31, w = tid >> 5;

        // 32 query rows + norms (half-warp shuffle reduce)
        {
            const float4* qsrc = (const float4*)(act + row0 * N_DIM);
            #pragma unroll
            for (int t = 0; t < 2; t++) {
                int fi = tid + t * 256;
                float4 v = qsrc[fi];
                ((float4*)S->xq)[fi] = v;
                float s = v.x * v.x + v.y * v.y + v.z * v.z + v.w * v.w;
                s += __shfl_down_sync(0xffffffffu, s, 8, 16);
                s += __shfl_down_sync(0xffffffffu, s, 4, 16);
                s += __shfl_down_sync(0xffffffffu, s, 2, 16);
                s += __shfl_down_sync(0xffffffffu, s, 1, 16);
                if ((lane & 15) == 0) S->qn[fi >> 4] = s;
            }
        }

        float m[4][6];
        #pragma unroll
        for (int r = 0; r < 4; r++)
            #pragma unroll
            for (int i = 0; i < 6; i++) m[r][i] = 3.4e38f;

        for (int t = 0; t < 2; t++) {
            __syncthreads();
            const float4* gsrc = (const float4*)(act + (jbase + t * 128) * N_DIM);
            #pragma unroll
            for (int it = 0; it < 8; it++) {
                int fi = tid + it * 256;
                float4 v = gsrc[fi];
                *(float4*)&S->tile[fi >> 4][(fi & 15) * 4] = v;
                float s = v.x * v.x + v.y * v.y + v.z * v.z + v.w * v.w;
                s += __shfl_down_sync(0xffffffffu, s, 8, 16);
                s += __shfl_down_sync(0xffffffffu, s, 4, 16);
                s += __shfl_down_sync(0xffffffffu, s, 2, 16);
                s += __shfl_down_sync(0xffffffffu, s, 1, 16);
                if ((lane & 15) == 0) S->jn[fi >> 4] = s;
            }
            __syncthreads();

            float acc[4][4];
            #pragma unroll
            for (int r = 0; r < 4; r++)
                #pragma unroll
                for (int s = 0; s < 4; s++) acc[r][s] = 0.f;

            #pragma unroll
            for (int c = 0; c < 8; c++) {      // 8-dim chunks
                float4 qr[4][2];
                #pragma unroll
                for (int r = 0; r < 4; r++) {
                    qr[r][0] = *(const float4*)&S->xq[4 * w + r][c * 8];
                    qr[r][1] = *(const float4*)&S->xq[4 * w + r][c * 8 + 4];
                }
                #pragma unroll
                for (int s = 0; s < 4; s++) {
                    const int j = lane + 32 * s;
                    const float4 b0 = *(const float4*)&S->tile[j][c * 8];
                    const float4 b1 = *(const float4*)&S->tile[j][c * 8 + 4];
                    #pragma unroll
                    for (int r = 0; r < 4; r++) {
                        float a = acc[r][s];
                        a = fmaf(qr[r][0].x, b0.x, a);
                        a = fmaf(qr[r][0].y, b0.y, a);
                        a = fmaf(qr[r][0].z, b0.z, a);
                        a = fmaf(qr[r][0].w, b0.w, a);
                        a = fmaf(qr[r][1].x, b1.x, a);
                        a = fmaf(qr[r][1].y, b1.y, a);
                        a = fmaf(qr[r][1].z, b1.z, a);
                        a = fmaf(qr[r][1].w, b1.w, a);
                        acc[r][s] = a;
                    }
                }
            }
            #pragma unroll
            for (int s = 0; s < 4; s++) {
                const float nj = S->jn[lane + 32 * s];
                #pragma unroll
                for (int r = 0; r < 4; r++) {
                    float v = fmaf(acc[r][s], -2.f, nj);
                    if (v < m[r][5]) {
                        m[r][5] = v;
                        #pragma unroll
                        for (int i = 5; i > 0; i--)
                            if (m[r][i] < m[r][i - 1]) {
                                float tm = m[r][i]; m[r][i] = m[r][i - 1]; m[r][i - 1] = tm;
                            }
                    }
                }
            }
        }

        // per-row: extract top-6 over lanes, add qn, store
        #pragma unroll
        for (int r = 0; r < 4; r++) {
            float l0 = m[r][0], l1 = m[r][1], l2 = m[r][2];
            float l3 = m[r][3], l4 = m[r][4], l5 = m[r][5];
            float keep = 3.4e38f;
            #pragma unroll
            for (int i = 0; i < 6; i++) {
                float mv = l0;
                #pragma unroll
                for (int off = 16; off; off >>= 1)
                    mv = fminf(mv, __shfl_xor_sync(0xffffffffu, mv, off));
                if (lane == i) keep = mv;
                unsigned msk = __ballot_sync(0xffffffffu, l0 == mv);
                if (lane == (__ffs(msk) - 1)) {
                    l0 = l1; l1 = l2; l2 = l3; l3 = l4; l4 = l5; l5 = 3.4e38f;
                }
            }
            if (lane < 6)
                g_t6[g][q][4 * w + r][lane] = keep + S->qn[4 * w + r];
        }
        __syncthreads();
        if (tid == 0) {
            __threadfence();
            int old = atomicAdd(&g_qc[g], 1);
            S->merge = (old == NQ - 1);
        }
        __syncthreads();
        if (S->merge) {
            __threadfence();
            if (tid < 32) {
                int kk = *kp; if (kk > 5) kk = 5;
                float best[6];
                #pragma unroll
                for (int i = 0; i < 6; i++) best[i] = 3.4e38f;
                #pragma unroll
                for (int qq = 0; qq < NQ; qq++) {
                    #pragma unroll
                    for (int i = 0; i < 6; i++) {
                        float v = g_t6[g][qq][tid][i];
                        if (v < best[5]) {
                            best[5] = v;
                            #pragma unroll
                            for (int j2 = 5; j2 > 0; j2--)
                                if (best[j2] < best[j2 - 1]) {
                                    float tm = best[j2]; best[j2] = best[j2 - 1]; best[j2 - 1] = tm;
                                }
                        }
                    }
                }
                g_logrho[row0 + tid] = logf(fmaxf(best[kk], 1e-12f));
            }
            if (tid == 0) g_qc[g] = 0;   // reset for graph replay
        }
    } else {
        // ================= PREP (256 thr, 4 elems/thread) ================
        PrepS* P = (PrepS*)sm;
        const int col = bx - NBLK_KNN;
        float s1 = 0.f, s2 = 0.f;
        #pragma unroll
        for (int t = 0; t < 4; t++) {
            float v = act[(tid + 256 * t) * N_DIM + col];
            P->u[tid + 256 * t] = v;
            s1 += v;
            s2 += v * v;
        }
        P->red[tid] = s1; __syncthreads();
        for (int st = 128; st > 0; st >>= 1) {
            if (tid < st) P->red[tid] += P->red[tid + st];
            __syncthreads();
        }
        float tot1 = P->red[0]; __syncthreads();
        P->red[tid] = s2; __syncthreads();
        for (int st = 128; st > 0; st >>= 1) {
            if (tid < st) P->red[tid] += P->red[tid + st];
            __syncthreads();
        }
        if (tid == 0) {
            const float Bf = (float)B_ROWS;
            float mean = tot1 / Bf;
            float var  = (P->red[0] - Bf * mean * mean) / (Bf - 1.0f);
            float stdv = sqrtf(fmaxf(var, 0.f));
            float h    = fmaxf(1.06f * stdv * 0.25f, 1e-4f);
            float ih   = 1.0f / h;
            g_invh[col] = ih;
            P->scale    = ih;
        }
        __syncthreads();
        const float sc = P->scale;
        #pragma unroll
        for (int t = 0; t < 4; t++)
            P->u[tid + 256 * t] *= sc;

        for (int kk2 = 2; kk2 <= B_ROWS; kk2 <<= 1) {
            for (int jj = kk2 >> 1; jj > 0; jj >>= 1) {
                __syncthreads();
                #pragma unroll
                for (int t = 0; t < 4; t++) {
                    int i = tid + 256 * t;
                    int ixj = i ^ jj;
                    if (ixj > i) {
                        bool up = ((i & kk2) == 0);
                        float a = P->u[i], b = P->u[ixj];
                        if ((a > b) == up) { P->u[i] = b; P->u[ixj] = a; }
                    }
                }
            }
        }
        __syncthreads();
        #pragma unroll
        for (int t = 0; t < 4; t++)
            g_cols[col * B_ROWS + tid + 256 * t] = P->u[tid + 256 * t];
    }
}

// ---------------------------------------------------------------------------
// Kernel 2: KDE — 64-query chunks, reflections folded into Hermite moments.
// grid = 512 (col*8+cp); block = 256: chunks cp (warps 0-3) and 15-cp
// (warps 4-7); 4 warps of moment accumulation, 2 Horner warps per chunk.
// ---------------------------------------------------------------------------
__global__ __launch_bounds__(256)
void k2(const int* __restrict__ kp, float* __restrict__ out) {
    __shared__ __align__(16) float u[B_ROWS];
    __shared__ float msum[2][4][NMOM];
    __shared__ float lsum[2][2];
    __shared__ int   bnd[2][4];
    __shared__ double dred[256];
    __shared__ int   s_col_last, s_master;

    const int tid  = threadIdx.x;
    const int lane = tid & 31;
    const int w    = tid >> 5;
    const int half = w >> 2;
    const int wl   = w & 3;
    const int col  = blockIdx.x >> 3;
    const int cp   = blockIdx.x & 7;
    const int chunk = half ? (15 - cp) : cp;

    ((float4*)u)[tid] = ((const float4*)(g_cols + col * B_ROWS))[tid];
    __syncthreads();

    const float ih = g_invh[col];
    const float c2 = 2.0f * ih;
    const int   q0 = chunk * 64;
    const float cen = 0.5f * (u[q0] + u[q0 + 63]);

    if (tid < 8) {
        int h2 = tid >> 2, i2 = tid & 3;
        int ch = h2 ? (15 - cp) : cp;
        float xmn = u[ch * 64], xmx = u[ch * 64 + 63];
        float tgt = (i2 == 0) ? xmn - TS : (i2 == 1) ? xmx + TS
                  : (i2 == 2) ? TS - xmn : c2 - TS - xmx;
        int pos = 0;
        #pragma unroll
        for (int step = 1024; step; step >>= 1) {
            int np = pos + step;
            if (np <= B_ROWS && u[np - 1] < tgt) pos = np;
        }
        bnd[h2][i2] = pos;
    }
    __syncthreads();
    const int a0 = bnd[half][0], b0 = bnd[half][1];
    const int bL = bnd[half][2], aR = bnd[half][3];

    // ---- Hermite moments over main + mirrored windows (4 warps) ----
    {
        constexpr float INV[NMOM] = {0.f, 1.f, 0.5f, 0.33333334f, 0.25f, 0.2f,
            0.16666667f, 0.14285715f, 0.125f, 0.11111111f};
        float M[NMOM];
        #pragma unroll
        for (int n = 0; n < NMOM; n++) M[n] = 0.f;
        const int t128 = wl * 32 + lane;

        #define HSTEP(arg) do {                                   \
            float uj_ = (arg);                                    \
            float wg_ = ex2(K2C * uj_ * uj_);                     \
            float bp_ = wg_, bc_ = wg_ * uj_;                     \
            M[0] += bp_; M[1] += bc_;                             \
            _Pragma("unroll")                                     \
            for (int n_ = 1; n_ < NMOM - 1; n_++) {               \
                float bn_ = fmaf(uj_, bc_, -bp_) * INV[n_ + 1];   \
                M[n_ + 1] += bn_; bp_ = bc_; bc_ = bn_;           \
            }                                                     \
        } while (0)

        for (int j = a0 + t128; j < b0; j += 128) HSTEP(u[j] - cen);
        for (int j = t128; j < bL; j += 128)      HSTEP(-u[j] - cen);
        for (int j = aR + t128; j < B_ROWS; j += 128) HSTEP(c2 - u[j] - cen);
        #undef HSTEP

        #pragma unroll
        for (int n = 0; n < NMOM; n++) {
            #pragma unroll
            for (int off = 16; off; off >>= 1)
                M[n] += __shfl_xor_sync(0xffffffffu, M[n], off);
        }
        if (lane == 0) {
            #pragma unroll
            for (int n = 0; n < NMOM; n++) msum[half][wl][n] = M[n];
        }
    }
    __syncthreads();

    // ---- per-query Horner (warps wl==0: queries 0-31, wl==1: 32-63) ----
    if (wl < 2) {
        float Mn[NMOM];
        #pragma unroll
        for (int n = 0; n < NMOM; n++)
            Mn[n] = (msum[half][0][n] + msum[half][1][n])
                  + (msum[half][2][n] + msum[half][3][n]);
        const float x = u[q0 + wl * 32 + lane];
        const float delta = x - cen;
        float f = Mn[NMOM - 1];
        #pragma unroll
        for (int n = NMOM - 2; n >= 0; n--)
            f = fmaf(f, delta, Mn[n]);

        const float Bf = (float)B_ROWS;
        const float scale = ih * (1.0f / (Bf * 2.5066282746310002f));
        float l = logf(f * scale + 1e-8f);
        #pragma unroll
        for (int off = 16; off; off >>= 1)
            l += __shfl_xor_sync(0xffffffffu, l, off);
        if (lane == 0) lsum[half][wl] = l;
    }
    __syncthreads();
    if (tid == 0) {
        g_partials[col * QCH2 + cp]        = lsum[0][0] + lsum[0][1];
        g_partials[col * QCH2 + (15 - cp)] = lsum[1][0] + lsum[1][1];
    }

    // ---- hierarchical completion ----
    __syncthreads();
    if (tid == 0) {
        __threadfence();
        int old = atomicAdd(&g_colc[col], 1);
        s_col_last = (old == 7);
    }
    __syncthreads();
    if (!s_col_last) return;
    __threadfence();

    // column winner: assemble this column's marginal entropy
    if (tid < 32) {
        float t = (tid < QCH2) ? g_partials[col * QCH2 + tid] : 0.f;
        #pragma unroll
        for (int off = 16; off; off >>= 1)
            t += __shfl_xor_sync(0xffffffffu, t, off);
        if (tid == 0) {
            out[1 + col] = -t / (float)B_ROWS;
            g_colc[col] = 0;   // reset for graph replay
        }
    }
    __syncthreads();
    if (tid == 0) {
        __threadfence();
        int old = atomicAdd(&g_done, 1);
        s_master = (old == N_DIM - 1);
    }
    __syncthreads();
    if (!s_master) return;
    __threadfence();

    // master: fp64 joint entropy
    {
        double s = 0.0;
        for (int i = tid; i < B_ROWS; i += 256) s += (double)g_logrho[i];
        dred[tid] = s; __syncthreads();
        for (int st = 128; st > 0; st >>= 1) {
            if (tid < st) dred[tid] += dred[tid + st];
            __syncthreads();
        }
        if (tid == 0) {
            const int k = *kp;
            const double EULER    = 0.5772156649015328606;
            const double DG_B     = 6.9309834448765934;     // psi(1024)
            const double LGAMMA33 = 81.55795945611503558;   // lgamma(64/2+1)
            const double LOG_PI   = 1.1447298858494001741;
            const double INV_LN2  = 1.4426950408889634074;
            double dg_k = -EULER;
            for (int i = 1; i < k; i++) dg_k += 1.0 / (double)i;
            double log_c_d = 0.5 * (double)N_DIM * LOG_PI - LGAMMA33;
            double mean_lr = dred[0] / (double)B_ROWS;
            double h_nats = -dg_k + DG_B + log_c_d + (double)N_DIM * 0.5 * mean_lr;
            out[0] = (float)(h_nats * INV_LN2);
            g_done = 0;   // reset for graph replay
        }
    }
}

// ---------------------------------------------------------------------------
extern "C" void kernel_launch(void* const* d_in, const int* in_sizes, int n_in,
                              void* d_out, int out_size) {
    const float* act = (const float*)d_in[0];
    const int*   kp  = (const int*)d_in[1];
    float* out = (float*)d_out;
    (void)in_sizes; (void)n_in; (void)out_size;

    k1<<<NBLK_KNN + N_DIM, 256>>>(act, kp);
    k2<<<NBLK_K2, 256>>>(kp, out);
}